// round 4
// baseline (speedup 1.0000x reference)
#include <cuda_runtime.h>
#include <cuda_bf16.h>
#include <cstdint>

// Problem constants: x (16, 64, 56, 56) fp32, K=7, PAD=3, STRIDE=1, DIL=1
// out (16, 64, 49, 3136) fp32 ; out[n,c,kk,l] = center[l] - patch_kk[l]
#define NC_TOTAL   1024      // 16*64 planes
#define H_IMG      56
#define W_IMG      56
#define L_IMG      (H_IMG * W_IMG)        // 3136
#define KWIN       7
#define KK         (KWIN * KWIN)          // 49
#define TILE_H     62                     // 3 + 56 + 3
#define TILE_W     64                     // 4 + 56 + 3 (+1 spare), keeps rows 16B-aligned
#define TILE_ELEMS (TILE_H * TILE_W)      // 3968 floats = 15872 B
#define THREADS    256
#define NCHUNK     (L_IMG / 4)            // 784 float4 chunks per plane

__global__ __launch_bounds__(THREADS)
void subtraction_kernel(const float* __restrict__ x, float* __restrict__ out) {
    __shared__ float tile[TILE_ELEMS];

    const int nc  = blockIdx.x;
    const int tid = threadIdx.x;

    // -------- Stage the (n,c) plane into smem with zero padding --------
    // tile[(h+3)*64 + (w+4)] = x[h][w]; everything else = 0.
    const float* __restrict__ src = x + (size_t)nc * L_IMG;
    #pragma unroll 4
    for (int idx = tid; idx < TILE_ELEMS; idx += THREADS) {
        const int r  = idx >> 6;       // / 64
        const int cc = idx & 63;       // % 64
        const int h  = r - 3;
        const int w  = cc - 4;
        float v = 0.0f;
        if ((unsigned)h < H_IMG && (unsigned)w < W_IMG)
            v = src[h * W_IMG + w];
        tile[idx] = v;
    }
    __syncthreads();

    float* __restrict__ outbase = out + (size_t)nc * (KK * L_IMG);

    // -------- Each thread: 4 contiguous L positions, all 49 offsets --------
    for (int chunk = tid; chunk < NCHUNK; chunk += THREADS) {
        const int l = chunk << 2;            // multiple of 4; stays inside one row
        const int h = l / W_IMG;
        const int w = l - h * W_IMG;         // multiple of 4

        // Center: aligned float4 (tile column w+4 is 16B aligned)
        const float4 c4 = *reinterpret_cast<const float4*>(
            &tile[(h + 3) * TILE_W + (w + 4)]);

        float* __restrict__ optr = outbase + l;

        #pragma unroll
        for (int i = 0; i < KWIN; i++) {
            // Patch element for offset (i,j), lane t: tile[(h+i)*64 + w + (j+1) + t]
            // j in [0,7), t in [0,4) -> offsets [1, 10] from prow. Load [0,12) as
            // three aligned LDS.128; the j-shifts become pure register selects.
            const float* prow = &tile[(h + i) * TILE_W + w];
            float e[12];
            *reinterpret_cast<float4*>(&e[0]) = *reinterpret_cast<const float4*>(prow);
            *reinterpret_cast<float4*>(&e[4]) = *reinterpret_cast<const float4*>(prow + 4);
            *reinterpret_cast<float4*>(&e[8]) = *reinterpret_cast<const float4*>(prow + 8);

            #pragma unroll
            for (int j = 0; j < KWIN; j++) {
                float4 o;
                o.x = c4.x - e[j + 1];
                o.y = c4.y - e[j + 2];
                o.z = c4.z - e[j + 3];
                o.w = c4.w - e[j + 4];
                // Output is write-once, never re-read: streaming (evict-first) store.
                __stcs(reinterpret_cast<float4*>(&optr[(i * KWIN + j) * L_IMG]), o);
            }
        }
    }
}

extern "C" void kernel_launch(void* const* d_in, const int* in_sizes, int n_in,
                              void* d_out, int out_size) {
    const float* x = (const float*)d_in[0];
    float* out     = (float*)d_out;
    subtraction_kernel<<<NC_TOTAL, THREADS>>>(x, out);
}

// round 5
// speedup vs baseline: 1.1188x; 1.1188x over previous
#include <cuda_runtime.h>
#include <cuda_bf16.h>
#include <cstdint>

// Problem constants: x (16, 64, 56, 56) fp32, K=7, PAD=3, STRIDE=1, DIL=1
// out (16, 64, 49, 3136) fp32 ; out[n,c,kk,l] = center[l] - patch_kk[l]
#define NC_TOTAL   1024      // 16*64 planes
#define H_IMG      56
#define W_IMG      56
#define L_IMG      (H_IMG * W_IMG)        // 3136
#define KWIN       7
#define KK         (KWIN * KWIN)          // 49
#define TILE_H     62                     // 3 + 56 + 3
#define TILE_W     64                     // 4 + 56 + 3 (+1 spare), keeps rows 16B-aligned
#define TILE_ELEMS (TILE_H * TILE_W)      // 3968 floats = 15872 B
#define THREADS    256
#define NCHUNK     (L_IMG / 4)            // 784 float4 chunks per plane
#define NBLOCKS    (NC_TOTAL * KWIN)      // 7168: one block per (plane, i-row)

__global__ __launch_bounds__(THREADS)
void subtraction_kernel(const float* __restrict__ x, float* __restrict__ out) {
    __shared__ float tile[TILE_ELEMS];

    const int bi  = blockIdx.x;
    const int nc  = bi / KWIN;           // plane index
    const int i   = bi - nc * KWIN;      // kernel row handled by this block
    const int tid = threadIdx.x;

    // -------- Stage the (n,c) plane into smem with zero padding --------
    // tile[(h+3)*64 + (w+4)] = x[h][w]; everything else = 0.
    const float* __restrict__ src = x + (size_t)nc * L_IMG;
    #pragma unroll 4
    for (int idx = tid; idx < TILE_ELEMS; idx += THREADS) {
        const int r  = idx >> 6;       // / 64
        const int cc = idx & 63;       // % 64
        const int h  = r - 3;
        const int w  = cc - 4;
        float v = 0.0f;
        if ((unsigned)h < H_IMG && (unsigned)w < W_IMG)
            v = src[h * W_IMG + w];
        tile[idx] = v;
    }
    __syncthreads();

    // This block writes only kk = i*7 .. i*7+6 : an 87.5 KB contiguous window.
    float* __restrict__ outbase = out + (size_t)nc * (KK * L_IMG)
                                      + (size_t)(i * KWIN) * L_IMG;

    // -------- Each thread: 4 contiguous L positions, 7 j-offsets --------
    for (int chunk = tid; chunk < NCHUNK; chunk += THREADS) {
        const int l = chunk << 2;            // multiple of 4; stays inside one row
        const int h = l / W_IMG;
        const int w = l - h * W_IMG;         // multiple of 4

        // Center: aligned float4 (tile column w+4 is 16B aligned)
        const float4 c4 = *reinterpret_cast<const float4*>(
            &tile[(h + 3) * TILE_W + (w + 4)]);

        // Patch row for this i: lane t of shift j reads tile[(h+i)*64 + w + (j+1) + t]
        // j in [0,7), t in [0,4) -> offsets [1, 10] from prow. Load [0,12) as three
        // aligned LDS.128; the j-shifts become pure register selects.
        const float* prow = &tile[(h + i) * TILE_W + w];
        float e[12];
        *reinterpret_cast<float4*>(&e[0]) = *reinterpret_cast<const float4*>(prow);
        *reinterpret_cast<float4*>(&e[4]) = *reinterpret_cast<const float4*>(prow + 4);
        *reinterpret_cast<float4*>(&e[8]) = *reinterpret_cast<const float4*>(prow + 8);

        float* __restrict__ optr = outbase + l;

        #pragma unroll
        for (int j = 0; j < KWIN; j++) {
            float4 o;
            o.x = c4.x - e[j + 1];
            o.y = c4.y - e[j + 2];
            o.z = c4.z - e[j + 3];
            o.w = c4.w - e[j + 4];
            // Output is write-once, never re-read: streaming (evict-first) store.
            __stcs(reinterpret_cast<float4*>(&optr[j * L_IMG]), o);
        }
    }
}

extern "C" void kernel_launch(void* const* d_in, const int* in_sizes, int n_in,
                              void* d_out, int out_size) {
    const float* x = (const float*)d_in[0];
    float* out     = (float*)d_out;
    subtraction_kernel<<<NBLOCKS, THREADS>>>(x, out);
}